// round 8
// baseline (speedup 1.0000x reference)
#include <cuda_runtime.h>
#include <cuda_fp16.h>
#include <math.h>
#include <stdint.h>

// Problem constants
#define BSZ   2048
#define INSZ  512
#define HSZ   512
#define OUTSZ 256
#define NSZ   32768
#define H3    (3*HSZ)
#define T_MAX 48
#define BH    (BSZ*HSZ)

// ---- generic GEMM tile (A0 + gather output) ----
#define BM 128
#define BN 128
#define STAGE_BYTES_G (2*BM*128)
#define STAGES 3
#define SMEM_G (STAGES*STAGE_BYTES_G)       // 98304

// ---- fused GRU-step GEMM tile ----
#define BM2 64
#define BN2 384          // 128 j-cols x 3 gates (weights pre-permuted)
#define ABYTES (BM2*128)             // 8192
#define WBYTES (BN2*128)             // 49152
#define STG_BYTES (ABYTES+WBYTES)    // 57344
#define STG_N 3
#define SMEM2 (STG_N*STG_BYTES)      // 172032

// ---------------- device scratch ----------------
__device__ float  d_h0fA[BH], d_h0fB[BH], d_h1fA[BH], d_h1fB[BH];
__device__ __half d_h0hA[BH], d_h0hB[BH], d_h1hA[BH], d_h1hB[BH];
__device__ float  d_A0 [BSZ*H3];
__device__ float  d_G1 [BSZ*H3];
__device__ __half d_Y1h[(size_t)T_MAX*BH];
__device__ __half d_xh   [BSZ*INSZ];
__device__ __half d_Wih0h[H3*INSZ];
__device__ __half d_Wouth[OUTSZ*HSZ];
__device__ __half d_Whh0p[H3*HSZ];   // permuted: row jg*384+gate*128+r <- gate*512+jg*128+r
__device__ __half d_Wih1p[H3*HSZ];
__device__ __half d_Whh1p[H3*HSZ];
__device__ int    d_first[BSZ];
__device__ int    d_rowoff[NSZ];
__device__ int    d_T[1];

// ---------------- setup kernels ----------------
__global__ void k_init_first(const int* __restrict__ psi) {
    int i = blockIdx.x * blockDim.x + threadIdx.x;
    if (i == 0) d_T[0] = 0;
    if (i < BH) {
        d_h0fA[i]=0.f; d_h1fA[i]=0.f;
        d_h0hA[i]=__float2half(0.f); d_h1hA[i]=__float2half(0.f);
    }
    if (i < NSZ) {
        if (i == 0 || psi[i] != psi[i-1]) d_first[psi[i]] = i;
    }
}

__global__ void k_rank(const int* __restrict__ psi) {
    int j = blockIdx.x * blockDim.x + threadIdx.x;
    if (j >= NSZ) return;
    int v = psi[j];
    int r = j - d_first[v];
    d_rowoff[j] = r * BH + v * HSZ;
    atomicMax(&d_T[0], r + 1);
}

__device__ __forceinline__ void conv4(const float* src, __half* dst, int si, int di) {
    float4 v = *(const float4*)(src + si);
    ((__half2*)(dst + di))[0] = __floats2half2_rn(v.x, v.y);
    ((__half2*)(dst + di))[1] = __floats2half2_rn(v.z, v.w);
}

// convert x, Wih0, Wout  (grid sized by the LARGEST job: BSZ*INSZ)
__global__ void k_convA(const float* __restrict__ x, const float* __restrict__ w0,
                        const float* __restrict__ wo) {
    int i = (blockIdx.x * blockDim.x + threadIdx.x) << 2;
    if (i < BSZ*INSZ)  conv4(x,  d_xh,    i, i);
    if (i < H3*INSZ)   conv4(w0, d_Wih0h, i, i);
    if (i < OUTSZ*HSZ) conv4(wo, d_Wouth, i, i);
}

// convert + gate-permute recurrent weights
__global__ void k_permw(const float* __restrict__ whh0, const float* __restrict__ wih1,
                        const float* __restrict__ whh1) {
    int i = (blockIdx.x * blockDim.x + threadIdx.x) << 2;
    if (i >= H3*HSZ) return;
    int row = i >> 9, col = i & 511;
    int gate = row >> 9, rr = row & 511;
    int jg = rr >> 7, r = rr & 127;
    int di = (jg*384 + gate*128 + r)*512 + col;
    conv4(whh0, d_Whh0p, i, di);
    conv4(wih1, d_Wih1p, i, di);
    conv4(whh1, d_Whh1p, i, di);
}

// ---------------- generic fp16 GEMM (A0 + gather), round-6 proven ----------------
__global__ __launch_bounds__(256, 2)
void gemm_fp16(const __half* __restrict__ A, const __half* __restrict__ W, float* __restrict__ C,
               int M, int N, int K,
               const int* __restrict__ a_off, const float* __restrict__ bias)
{
    extern __shared__ uint32_t sm[];
    const uint32_t smaddr = (uint32_t)__cvta_generic_to_shared(sm);

    const int tid  = threadIdx.x;
    const int lane = tid & 31;
    const int warp = tid >> 5;
    const int wm   = warp >> 2;
    const int wn   = warp & 3;
    const int g    = lane >> 2;
    const int q    = lane & 3;

    const int row0 = blockIdx.y * BM;
    const int col0 = blockIdx.x * BN;

    const int lm   = tid >> 1;
    const int lkg0 = (tid & 1) * 4;

    long arow = a_off ? (long)a_off[row0 + lm] : (long)(row0 + lm) * K;
    const __half* agp = A + arow;
    const __half* wgp = W + (long)(col0 + lm) * K;

    uint32_t soffB[4];
#pragma unroll
    for (int j = 0; j < 4; j++)
        soffB[j] = (uint32_t)(lm * 128 + (((lkg0 + j) ^ (lm & 7)) << 4));

#define LOAD_STAGE_G(st, kt) do {                                            \
        uint32_t dA = smaddr + (st)*STAGE_BYTES_G;                           \
        uint32_t dW = dA + BM*128;                                           \
        const __half* ga = agp + (size_t)(kt)*64;                            \
        const __half* gw = wgp + (size_t)(kt)*64;                            \
        _Pragma("unroll")                                                    \
        for (int j = 0; j < 4; j++) {                                        \
            asm volatile("cp.async.cg.shared.global [%0], [%1], 16;"         \
                         :: "r"(dA + soffB[j]), "l"(ga + (lkg0 + j)*8));     \
            asm volatile("cp.async.cg.shared.global [%0], [%1], 16;"         \
                         :: "r"(dW + soffB[j]), "l"(gw + (lkg0 + j)*8));     \
        }                                                                    \
    } while (0)

    float acc[4][4][4];
#pragma unroll
    for (int a = 0; a < 4; a++)
#pragma unroll
        for (int b = 0; b < 4; b++)
#pragma unroll
            for (int c = 0; c < 4; c++) acc[a][b][c] = 0.f;

    const int KT = K / 64;

#pragma unroll
    for (int s = 0; s < STAGES-1; s++) {
        LOAD_STAGE_G(s, s);
        asm volatile("cp.async.commit_group;" ::: "memory");
    }

    const uint32_t a_row15 = lane & 15;
    const uint32_t a_hi    = lane >> 4;
    const uint32_t x7      = lane & 7;
    const uint32_t w_hi    = lane >> 3;

    uint32_t aRowOff[4], wRowOff[4];
#pragma unroll
    for (int mi = 0; mi < 4; mi++)
        aRowOff[mi] = (uint32_t)((wm*64 + mi*16 + a_row15) * 128);
#pragma unroll
    for (int ni = 0; ni < 4; ni++)
        wRowOff[ni] = (uint32_t)((BM*128) + (wn*32 + ni*8 + x7) * 128);

    for (int kt = 0; kt < KT; kt++) {
        asm volatile("cp.async.wait_group %0;" :: "n"(STAGES-2) : "memory");
        __syncthreads();
        int ktn = kt + STAGES - 1;
        if (ktn < KT) LOAD_STAGE_G(ktn % STAGES, ktn);
        asm volatile("cp.async.commit_group;" ::: "memory");

        const uint32_t sbase = smaddr + (kt % STAGES)*STAGE_BYTES_G;
#pragma unroll
        for (int kp = 0; kp < 2; kp++) {
            uint32_t wq[4][4];
            const uint32_t wsw = ((4*kp + w_hi) ^ x7) << 4;
#pragma unroll
            for (int ni = 0; ni < 4; ni++) {
                asm volatile("ldmatrix.sync.aligned.m8n8.x4.shared.b16 {%0,%1,%2,%3}, [%4];"
                    : "=r"(wq[ni][0]), "=r"(wq[ni][1]), "=r"(wq[ni][2]), "=r"(wq[ni][3])
                    : "r"(sbase + wRowOff[ni] + wsw));
            }
#pragma unroll
            for (int kk2 = 0; kk2 < 2; kk2++) {
                const int kk = 2*kp + kk2;
                const uint32_t asw = ((2*kk + a_hi) ^ x7) << 4;
                uint32_t af[4][4];
#pragma unroll
                for (int mi = 0; mi < 4; mi++) {
                    asm volatile("ldmatrix.sync.aligned.m8n8.x4.shared.b16 {%0,%1,%2,%3}, [%4];"
                        : "=r"(af[mi][0]), "=r"(af[mi][1]), "=r"(af[mi][2]), "=r"(af[mi][3])
                        : "r"(sbase + aRowOff[mi] + asw));
                }
#pragma unroll
                for (int mi = 0; mi < 4; mi++)
#pragma unroll
                    for (int ni = 0; ni < 4; ni++)
                        asm volatile(
                            "mma.sync.aligned.m16n8k16.row.col.f32.f16.f16.f32 "
                            "{%0,%1,%2,%3}, {%4,%5,%6,%7}, {%8,%9}, {%0,%1,%2,%3};"
                            : "+f"(acc[mi][ni][0]), "+f"(acc[mi][ni][1]),
                              "+f"(acc[mi][ni][2]), "+f"(acc[mi][ni][3])
                            : "r"(af[mi][0]), "r"(af[mi][1]), "r"(af[mi][2]), "r"(af[mi][3]),
                              "r"(wq[ni][2*kk2]), "r"(wq[ni][2*kk2+1]));
            }
        }
    }

#pragma unroll
    for (int mi = 0; mi < 4; mi++) {
        int r0 = row0 + wm*64 + mi*16 + g;
#pragma unroll
        for (int ni = 0; ni < 4; ni++) {
            int c = col0 + wn*32 + ni*8 + 2*q;
            float b0 = 0.f, b1 = 0.f;
            if (bias) { b0 = bias[c]; b1 = bias[c+1]; }
            *(float2*)(C + (size_t)r0     * N + c) = make_float2(acc[mi][ni][0]+b0, acc[mi][ni][1]+b1);
            *(float2*)(C + (size_t)(r0+8) * N + c) = make_float2(acc[mi][ni][2]+b0, acc[mi][ni][3]+b1);
        }
    }
#undef LOAD_STAGE_G
}

// ---------------- fused GRU-step GEMM ----------------
// GEMM: acc[64 x (3 gates x 128 j)] = Ah[64,512] * Wp^T (Wp pre-permuted, rows contiguous)
// z=0 (or kernel B): GRU epilogue.  z=1 (kernel A only): store acc+bias_z1 -> Gstore.
__global__ __launch_bounds__(256, 1)
void gru_fused(const __half* __restrict__ Aa, const __half* __restrict__ Wa,
               const __half* __restrict__ Ab, const __half* __restrict__ Wb,
               int acc_is_x,
               const float* __restrict__ Xg, const float* __restrict__ Gg,
               const float* __restrict__ bias_acc, const float* __restrict__ bias_z1,
               const float* __restrict__ h_in, float* __restrict__ h_out,
               __half* __restrict__ hh_out, __half* __restrict__ y_out,
               float* __restrict__ Gstore, int t)
{
    if (t >= d_T[0]) return;

    const bool storeG = (blockIdx.z == 1);
    const __half* A = storeG ? Ab : Aa;
    const __half* W = storeG ? Wb : Wa;

    extern __shared__ uint32_t sm[];
    const uint32_t smaddr = (uint32_t)__cvta_generic_to_shared(sm);

    const int tid  = threadIdx.x;
    const int lane = tid & 31;
    const int warp = tid >> 5;
    const int wm   = warp >> 2;   // 0..1 (rows)
    const int wn   = warp & 3;    // 0..3 (j-cols)

    const int row0 = blockIdx.y * BM2;
    const int jg   = blockIdx.x;           // 0..3

    // ---- loaders ----
    const int a_row = tid >> 2;
    const int a_g0  = (tid & 3) * 2;
    const __half* agp = A + (long)(row0 + a_row) * 512;
    uint32_t aoff[2];
#pragma unroll
    for (int j = 0; j < 2; j++)
        aoff[j] = (uint32_t)(a_row*128 + (((a_g0 + j) ^ (a_row & 7)) << 4));

    const int w_row0 = tid & 127;
    const int w_g0   = (tid >> 7) * 4;
    const __half* wgp = W + (long)(jg*384 + w_row0) * 512;
    uint32_t woff[3][4];
#pragma unroll
    for (int i = 0; i < 3; i++)
#pragma unroll
        for (int j = 0; j < 4; j++)
            woff[i][j] = (uint32_t)((w_row0 + i*128)*128 + (((w_g0 + j) ^ (w_row0 & 7)) << 4));

#define LOAD_STAGE2(st, kt) do {                                              \
        uint32_t dA = smaddr + (st)*STG_BYTES;                                \
        uint32_t dW = dA + ABYTES;                                            \
        const __half* ga = agp + (kt)*64;                                     \
        const __half* gw = wgp + (kt)*64;                                     \
        _Pragma("unroll")                                                     \
        for (int j = 0; j < 2; j++)                                           \
            asm volatile("cp.async.cg.shared.global [%0], [%1], 16;"          \
                         :: "r"(dA + aoff[j]), "l"(ga + (a_g0 + j)*8));       \
        _Pragma("unroll")                                                     \
        for (int i = 0; i < 3; i++)                                           \
            _Pragma("unroll")                                                 \
            for (int j = 0; j < 4; j++)                                       \
                asm volatile("cp.async.cg.shared.global [%0], [%1], 16;"      \
                             :: "r"(dW + woff[i][j]),                         \
                                "l"(gw + (size_t)i*128*512 + (w_g0 + j)*8));  \
    } while (0)

    float acc[2][3][4][4];   // [mi][gate][ni][e]
#pragma unroll
    for (int a = 0; a < 2; a++)
#pragma unroll
        for (int b = 0; b < 3; b++)
#pragma unroll
            for (int c = 0; c < 4; c++)
#pragma unroll
                for (int e = 0; e < 4; e++) acc[a][b][c][e] = 0.f;

#pragma unroll
    for (int s = 0; s < STG_N-1; s++) {
        LOAD_STAGE2(s, s);
        asm volatile("cp.async.commit_group;" ::: "memory");
    }

    const uint32_t a_row15 = lane & 15;
    const uint32_t a_hi    = lane >> 4;
    const uint32_t x7      = lane & 7;
    const uint32_t w_hi    = lane >> 3;

    uint32_t aRowOff[2];
#pragma unroll
    for (int mi = 0; mi < 2; mi++)
        aRowOff[mi] = (uint32_t)((wm*32 + mi*16 + a_row15) * 128);
    uint32_t wRowOff[3][4];
#pragma unroll
    for (int g3 = 0; g3 < 3; g3++)
#pragma unroll
        for (int ni = 0; ni < 4; ni++)
            wRowOff[g3][ni] = (uint32_t)(ABYTES + (g3*128 + wn*32 + ni*8 + x7) * 128);

    for (int kt = 0; kt < 8; kt++) {
        asm volatile("cp.async.wait_group %0;" :: "n"(STG_N-2) : "memory");
        __syncthreads();
        int ktn = kt + STG_N - 1;
        if (ktn < 8) LOAD_STAGE2(ktn % STG_N, ktn);
        asm volatile("cp.async.commit_group;" ::: "memory");

        const uint32_t sbase = smaddr + (kt % STG_N)*STG_BYTES;
#pragma unroll
        for (int kp = 0; kp < 2; kp++) {
            uint32_t wq[3][4][4];
            const uint32_t wsw = ((4*kp + w_hi) ^ x7) << 4;
#pragma unroll
            for (int g3 = 0; g3 < 3; g3++)
#pragma unroll
                for (int ni = 0; ni < 4; ni++)
                    asm volatile("ldmatrix.sync.aligned.m8n8.x4.shared.b16 {%0,%1,%2,%3}, [%4];"
                        : "=r"(wq[g3][ni][0]), "=r"(wq[g3][ni][1]),
                          "=r"(wq[g3][ni][2]), "=r"(wq[g3][ni][3])
                        : "r"(sbase + wRowOff[g3][ni] + wsw));
#pragma unroll
            for (int kk2 = 0; kk2 < 2; kk2++) {
                const int kk = 2*kp + kk2;
                const uint32_t asw = ((2*kk + a_hi) ^ x7) << 4;
                uint32_t af[2][4];
#pragma unroll
                for (int mi = 0; mi < 2; mi++)
                    asm volatile("ldmatrix.sync.aligned.m8n8.x4.shared.b16 {%0,%1,%2,%3}, [%4];"
                        : "=r"(af[mi][0]), "=r"(af[mi][1]), "=r"(af[mi][2]), "=r"(af[mi][3])
                        : "r"(sbase + aRowOff[mi] + asw));
#pragma unroll
                for (int mi = 0; mi < 2; mi++)
#pragma unroll
                    for (int g3 = 0; g3 < 3; g3++)
#pragma unroll
                        for (int ni = 0; ni < 4; ni++)
                            asm volatile(
                                "mma.sync.aligned.m16n8k16.row.col.f32.f16.f16.f32 "
                                "{%0,%1,%2,%3}, {%4,%5,%6,%7}, {%8,%9}, {%0,%1,%2,%3};"
                                : "+f"(acc[mi][g3][ni][0]), "+f"(acc[mi][g3][ni][1]),
                                  "+f"(acc[mi][g3][ni][2]), "+f"(acc[mi][g3][ni][3])
                                : "r"(af[mi][0]), "r"(af[mi][1]), "r"(af[mi][2]), "r"(af[mi][3]),
                                  "r"(wq[g3][ni][2*kk2]), "r"(wq[g3][ni][2*kk2+1]));
            }
        }
    }

    // ---- epilogue ----
    const int g8 = lane >> 2, q = lane & 3;

    if (storeG) {
#pragma unroll
        for (int mi = 0; mi < 2; mi++)
#pragma unroll
            for (int rsel = 0; rsel < 2; rsel++) {
                int R = row0 + wm*32 + mi*16 + g8 + rsel*8;
#pragma unroll
                for (int g3 = 0; g3 < 3; g3++)
#pragma unroll
                    for (int ni = 0; ni < 4; ni++) {
                        int col = g3*512 + jg*128 + wn*32 + ni*8 + 2*q;
                        float2 v = make_float2(
                            acc[mi][g3][ni][rsel*2+0] + bias_z1[col],
                            acc[mi][g3][ni][rsel*2+1] + bias_z1[col+1]);
                        *(float2*)(Gstore + (size_t)R*H3 + col) = v;
                    }
            }
        return;
    }

#pragma unroll
    for (int mi = 0; mi < 2; mi++)
#pragma unroll
        for (int rsel = 0; rsel < 2; rsel++) {
            int R = row0 + wm*32 + mi*16 + g8 + rsel*8;
#pragma unroll
            for (int ni = 0; ni < 4; ni++) {
                int j = jg*128 + wn*32 + ni*8 + 2*q;
                float2 hold = *(const float2*)(h_in + (size_t)R*HSZ + j);
                float hn[2];
#pragma unroll
                for (int c = 0; c < 2; c++) {
                    int cr = 0*512 + j + c, cz = 1*512 + j + c, cn = 2*512 + j + c;
                    float xr, xz, xn, gr, gz, gn;
                    if (acc_is_x) {
                        xr = acc[mi][0][ni][rsel*2+c] + bias_acc[cr];
                        xz = acc[mi][1][ni][rsel*2+c] + bias_acc[cz];
                        xn = acc[mi][2][ni][rsel*2+c] + bias_acc[cn];
                        const float* gp = Gg + (size_t)R*H3;
                        gr = gp[cr]; gz = gp[cz]; gn = gp[cn];
                    } else {
                        const float* xp = Xg + (size_t)R*H3;
                        xr = xp[cr]; xz = xp[cz]; xn = xp[cn];
                        gr = acc[mi][0][ni][rsel*2+c] + bias_acc[cr];
                        gz = acc[mi][1][ni][rsel*2+c] + bias_acc[cz];
                        gn = acc[mi][2][ni][rsel*2+c] + bias_acc[cn];
                    }
                    float r = 1.f / (1.f + expf(-(xr + gr)));
                    float z = 1.f / (1.f + expf(-(xz + gz)));
                    float n = tanhf(xn + r * gn);
                    float h = (c == 0) ? hold.x : hold.y;
                    hn[c] = (1.f - z) * n + z * h;
                }
                *(float2*)(h_out + (size_t)R*HSZ + j) = make_float2(hn[0], hn[1]);
                __half2 hh = __floats2half2_rn(hn[0], hn[1]);
                *(__half2*)(hh_out + (size_t)R*HSZ + j) = hh;
                if (y_out)
                    *(__half2*)(y_out + (size_t)R*HSZ + j) = hh;
            }
        }
#undef LOAD_STAGE2
}

// ---------------- host launch ----------------
extern "C" void kernel_launch(void* const* d_in, const int* in_sizes, int n_in,
                              void* d_out, int out_size)
{
    const float* x    = (const float*)d_in[0];
    const float* Wih0 = (const float*)d_in[1];
    const float* Whh0 = (const float*)d_in[2];
    const float* bih0 = (const float*)d_in[3];
    const float* bhh0 = (const float*)d_in[4];
    const float* Wih1 = (const float*)d_in[5];
    const float* Whh1 = (const float*)d_in[6];
    const float* bih1 = (const float*)d_in[7];
    const float* bhh1 = (const float*)d_in[8];
    const float* Wout = (const float*)d_in[9];
    const float* bout = (const float*)d_in[10];
    const int*   psi  = (const int*)d_in[11];
    float* out = (float*)d_out;

    cudaFuncSetAttribute(gemm_fp16,  cudaFuncAttributeMaxDynamicSharedMemorySize, SMEM_G);
    cudaFuncSetAttribute(gru_fused,  cudaFuncAttributeMaxDynamicSharedMemorySize, SMEM2);

    float *p_h0fA,*p_h0fB,*p_h1fA,*p_h1fB,*p_A0,*p_G1;
    __half *p_h0hA,*p_h0hB,*p_h1hA,*p_h1hB,*p_Y1h,*p_xh,*p_Wih0h,*p_Wouth,*p_Whh0p,*p_Wih1p,*p_Whh1p;
    int *p_rowoff;
    cudaGetSymbolAddress((void**)&p_h0fA, d_h0fA);
    cudaGetSymbolAddress((void**)&p_h0fB, d_h0fB);
    cudaGetSymbolAddress((void**)&p_h1fA, d_h1fA);
    cudaGetSymbolAddress((void**)&p_h1fB, d_h1fB);
    cudaGetSymbolAddress((void**)&p_h0hA, d_h0hA);
    cudaGetSymbolAddress((void**)&p_h0hB, d_h0hB);
    cudaGetSymbolAddress((void**)&p_h1hA, d_h1hA);
    cudaGetSymbolAddress((void**)&p_h1hB, d_h1hB);
    cudaGetSymbolAddress((void**)&p_A0,   d_A0);
    cudaGetSymbolAddress((void**)&p_G1,   d_G1);
    cudaGetSymbolAddress((void**)&p_Y1h,  d_Y1h);
    cudaGetSymbolAddress((void**)&p_xh,   d_xh);
    cudaGetSymbolAddress((void**)&p_Wih0h,d_Wih0h);
    cudaGetSymbolAddress((void**)&p_Wouth,d_Wouth);
    cudaGetSymbolAddress((void**)&p_Whh0p,d_Whh0p);
    cudaGetSymbolAddress((void**)&p_Wih1p,d_Wih1p);
    cudaGetSymbolAddress((void**)&p_Whh1p,d_Whh1p);
    cudaGetSymbolAddress((void**)&p_rowoff, d_rowoff);

    const int PWI = (BH + 255) / 256;

    // launches 0..3 setup, 4 = A0 GEMM, 5 = first gru_fused (ncu -s 5 target)
    k_init_first<<<PWI, 256>>>(psi);
    k_rank<<<(NSZ + 255) / 256, 256>>>(psi);
    k_convA<<<(BSZ*INSZ/4 + 255)/256, 256>>>(x, Wih0, Wout);   // FIXED: grid covers BSZ*INSZ
    k_permw<<<(H3*HSZ/4  + 255)/256, 256>>>(Whh0, Wih1, Whh1);

    // A0 = x . Wih0^T + bih0   [2048,1536] fp32
    {
        dim3 grid(H3 / BN, BSZ / BM);
        gemm_fp16<<<grid, 256, SMEM_G>>>(p_xh, p_Wih0h, p_A0, BSZ, H3, INSZ, nullptr, bih0);
    }

    float  *h0f_in = p_h0fA, *h0f_out = p_h0fB;
    float  *h1f_in = p_h1fA, *h1f_out = p_h1fB;
    __half *h0h_in = p_h0hA, *h0h_out = p_h0hB;
    __half *h1h_in = p_h1hA, *h1h_out = p_h1hB;

    for (int t = 0; t < T_MAX; t++) {
        // Kernel A: z=0 -> h0 update (G0 in-register, A0 from gmem); z=1 -> G1 = h1.Whh1^T + bhh1
        gru_fused<<<dim3(4, BSZ/BM2, 2), 256, SMEM2>>>(
            h0h_in, p_Whh0p, h1h_in, p_Whh1p,
            /*acc_is_x=*/0, p_A0, nullptr, bhh0, bhh1,
            h0f_in, h0f_out, h0h_out, nullptr, p_G1, t);

        // Kernel B: A1 = h0_new . Wih1^T (in-register) + G1 -> h1 update + Y1[t]
        gru_fused<<<dim3(4, BSZ/BM2, 1), 256, SMEM2>>>(
            h0h_out, p_Wih1p, h0h_out, p_Wih1p,
            /*acc_is_x=*/1, nullptr, p_G1, bih1, nullptr,
            h1f_in, h1f_out, h1h_out, p_Y1h + (size_t)t*BH, nullptr, t);

        // ping-pong
        float*  tf;
        __half* th;
        tf = h0f_in; h0f_in = h0f_out; h0f_out = tf;
        tf = h1f_in; h1f_in = h1f_out; h1f_out = tf;
        th = h0h_in; h0h_in = h0h_out; h0h_out = th;
        th = h1h_in; h1h_in = h1h_out; h1h_out = th;
    }

    // gathered output GEMM: out[N, OUT] = Y1h[rowoff[j]] . Wout^T + bout
    {
        dim3 grid(OUTSZ / BN, NSZ / BM);
        gemm_fp16<<<grid, 256, SMEM_G>>>(p_Y1h, p_Wouth, out, NSZ, OUTSZ, HSZ, p_rowoff, bout);
    }

    (void)in_sizes; (void)n_in; (void)out_size;
}

// round 9
// speedup vs baseline: 1.6458x; 1.6458x over previous
#include <cuda_runtime.h>
#include <cuda_fp16.h>
#include <math.h>
#include <stdint.h>

// Problem constants
#define BSZ   2048
#define INSZ  512
#define HSZ   512
#define OUTSZ 256
#define NSZ   32768
#define H3    (3*HSZ)
#define T_MAX 48
#define BH    (BSZ*HSZ)

#define BM 128
#define BN 128
#define STAGE_BYTES_G (2*BM*128)
#define STAGES 3
#define SMEM_G (STAGES*STAGE_BYTES_G)       // 98304

// ---------------- device scratch ----------------
__device__ float  d_h0fA[BH], d_h0fB[BH], d_h1fA[BH], d_h1fB[BH];
__device__ __half d_h0hA[BH], d_h0hB[BH], d_h1hA[BH], d_h1hB[BH];
__device__ float  d_A0[BSZ*H3];
__device__ float  d_G0[BSZ*H3];
__device__ float  d_G1[BSZ*H3];
__device__ float  d_A1[BSZ*H3];
__device__ __half d_Y1h[(size_t)T_MAX*BH];
__device__ __half d_xh   [BSZ*INSZ];
__device__ __half d_Wih0h[H3*INSZ];
__device__ __half d_Whh0h[H3*HSZ];
__device__ __half d_Wih1h[H3*HSZ];
__device__ __half d_Whh1h[H3*HSZ];
__device__ __half d_Wouth[OUTSZ*HSZ];
__device__ int    d_first[BSZ];
__device__ int    d_rowoff[NSZ];
__device__ int    d_T[1];

// ---------------- setup kernels ----------------
__global__ void k_init_first(const int* __restrict__ psi) {
    int i = blockIdx.x * blockDim.x + threadIdx.x;
    if (i == 0) d_T[0] = 0;
    if (i < BH) {
        d_h0fA[i]=0.f; d_h0fB[i]=0.f; d_h1fA[i]=0.f; d_h1fB[i]=0.f;
        __half z = __float2half(0.f);
        d_h0hA[i]=z; d_h0hB[i]=z; d_h1hA[i]=z; d_h1hB[i]=z;
    }
    if (i < NSZ) {
        if (i == 0 || psi[i] != psi[i-1]) d_first[psi[i]] = i;
    }
}

__global__ void k_rank(const int* __restrict__ psi) {
    int j = blockIdx.x * blockDim.x + threadIdx.x;
    if (j >= NSZ) return;
    int v = psi[j];
    int r = j - d_first[v];
    d_rowoff[j] = r * BH + v * HSZ;
    atomicMax(&d_T[0], r + 1);
}

__device__ __forceinline__ void conv4(const float* src, __half* dst, int i) {
    float4 v = *(const float4*)(src + i);
    ((__half2*)(dst + i))[0] = __floats2half2_rn(v.x, v.y);
    ((__half2*)(dst + i))[1] = __floats2half2_rn(v.z, v.w);
}

// convert x, Wih0, Wout (grid sized by the largest job: BSZ*INSZ)
__global__ void k_convA(const float* __restrict__ x, const float* __restrict__ w0,
                        const float* __restrict__ wo) {
    int i = (blockIdx.x * blockDim.x + threadIdx.x) << 2;
    if (i < BSZ*INSZ)  conv4(x,  d_xh,    i);
    if (i < H3*INSZ)   conv4(w0, d_Wih0h, i);
    if (i < OUTSZ*HSZ) conv4(wo, d_Wouth, i);
}

// convert recurrent weights (row-major, no permutation)
__global__ void k_convB(const float* __restrict__ whh0, const float* __restrict__ wih1,
                        const float* __restrict__ whh1) {
    int i = (blockIdx.x * blockDim.x + threadIdx.x) << 2;
    if (i >= H3*HSZ) return;
    conv4(whh0, d_Whh0h, i);
    conv4(wih1, d_Wih1h, i);
    conv4(whh1, d_Whh1h, i);
}

// ---------------- fp16 mma GEMM (round-6 proven), 3 operand sets via blockIdx.z ----------------
// C[M,N] = A[M,K] * W[N,K]^T (+bias). A rows optionally gathered via a_off.
// chk: z==0 runs iff 0<=t0<T; z>=1 runs iff 0<=t1<T.
__global__ __launch_bounds__(256, 2)
void gemm3(const __half* __restrict__ Aa, const __half* __restrict__ Wa, float* __restrict__ Ca,
           const __half* __restrict__ Ab, const __half* __restrict__ Wb, float* __restrict__ Cb,
           const __half* __restrict__ Ac, const __half* __restrict__ Wc, float* __restrict__ Cc,
           int M, int N, int K,
           const int* __restrict__ a_off, const float* __restrict__ bias,
           int t0, int t1, int chk)
{
    if (chk) {
        int tt = (blockIdx.z == 0) ? t0 : t1;
        if (tt < 0 || tt >= d_T[0]) return;
    }
    const __half* A = (blockIdx.z == 0) ? Aa : ((blockIdx.z == 1) ? Ab : Ac);
    const __half* W = (blockIdx.z == 0) ? Wa : ((blockIdx.z == 1) ? Wb : Wc);
    float*        C = (blockIdx.z == 0) ? Ca : ((blockIdx.z == 1) ? Cb : Cc);

    extern __shared__ uint32_t sm[];
    const uint32_t smaddr = (uint32_t)__cvta_generic_to_shared(sm);

    const int tid  = threadIdx.x;
    const int lane = tid & 31;
    const int warp = tid >> 5;
    const int wm   = warp >> 2;
    const int wn   = warp & 3;
    const int g    = lane >> 2;
    const int q    = lane & 3;

    const int row0 = blockIdx.y * BM;
    const int col0 = blockIdx.x * BN;

    const int lm   = tid >> 1;
    const int lkg0 = (tid & 1) * 4;

    long arow = a_off ? (long)a_off[row0 + lm] : (long)(row0 + lm) * K;
    const __half* agp = A + arow;
    const __half* wgp = W + (long)(col0 + lm) * K;

    uint32_t soffB[4];
#pragma unroll
    for (int j = 0; j < 4; j++)
        soffB[j] = (uint32_t)(lm * 128 + (((lkg0 + j) ^ (lm & 7)) << 4));

#define LOAD_STAGE_G(st, kt) do {                                            \
        uint32_t dA = smaddr + (st)*STAGE_BYTES_G;                           \
        uint32_t dW = dA + BM*128;                                           \
        const __half* ga = agp + (size_t)(kt)*64;                            \
        const __half* gw = wgp + (size_t)(kt)*64;                            \
        _Pragma("unroll")                                                    \
        for (int j = 0; j < 4; j++) {                                        \
            asm volatile("cp.async.cg.shared.global [%0], [%1], 16;"         \
                         :: "r"(dA + soffB[j]), "l"(ga + (lkg0 + j)*8));     \
            asm volatile("cp.async.cg.shared.global [%0], [%1], 16;"         \
                         :: "r"(dW + soffB[j]), "l"(gw + (lkg0 + j)*8));     \
        }                                                                    \
    } while (0)

    float acc[4][4][4];
#pragma unroll
    for (int a = 0; a < 4; a++)
#pragma unroll
        for (int b = 0; b < 4; b++)
#pragma unroll
            for (int c = 0; c < 4; c++) acc[a][b][c] = 0.f;

    const int KT = K / 64;

#pragma unroll
    for (int s = 0; s < STAGES-1; s++) {
        LOAD_STAGE_G(s, s);
        asm volatile("cp.async.commit_group;" ::: "memory");
    }

    const uint32_t a_row15 = lane & 15;
    const uint32_t a_hi    = lane >> 4;
    const uint32_t x7      = lane & 7;
    const uint32_t w_hi    = lane >> 3;

    uint32_t aRowOff[4], wRowOff[4];
#pragma unroll
    for (int mi = 0; mi < 4; mi++)
        aRowOff[mi] = (uint32_t)((wm*64 + mi*16 + a_row15) * 128);
#pragma unroll
    for (int ni = 0; ni < 4; ni++)
        wRowOff[ni] = (uint32_t)((BM*128) + (wn*32 + ni*8 + x7) * 128);

    for (int kt = 0; kt < KT; kt++) {
        asm volatile("cp.async.wait_group %0;" :: "n"(STAGES-2) : "memory");
        __syncthreads();
        int ktn = kt + STAGES - 1;
        if (ktn < KT) LOAD_STAGE_G(ktn % STAGES, ktn);
        asm volatile("cp.async.commit_group;" ::: "memory");

        const uint32_t sbase = smaddr + (kt % STAGES)*STAGE_BYTES_G;
#pragma unroll
        for (int kp = 0; kp < 2; kp++) {
            uint32_t wq[4][4];
            const uint32_t wsw = ((4*kp + w_hi) ^ x7) << 4;
#pragma unroll
            for (int ni = 0; ni < 4; ni++) {
                asm volatile("ldmatrix.sync.aligned.m8n8.x4.shared.b16 {%0,%1,%2,%3}, [%4];"
                    : "=r"(wq[ni][0]), "=r"(wq[ni][1]), "=r"(wq[ni][2]), "=r"(wq[ni][3])
                    : "r"(sbase + wRowOff[ni] + wsw));
            }
#pragma unroll
            for (int kk2 = 0; kk2 < 2; kk2++) {
                const int kk = 2*kp + kk2;
                const uint32_t asw = ((2*kk + a_hi) ^ x7) << 4;
                uint32_t af[4][4];
#pragma unroll
                for (int mi = 0; mi < 4; mi++) {
                    asm volatile("ldmatrix.sync.aligned.m8n8.x4.shared.b16 {%0,%1,%2,%3}, [%4];"
                        : "=r"(af[mi][0]), "=r"(af[mi][1]), "=r"(af[mi][2]), "=r"(af[mi][3])
                        : "r"(sbase + aRowOff[mi] + asw));
                }
#pragma unroll
                for (int mi = 0; mi < 4; mi++)
#pragma unroll
                    for (int ni = 0; ni < 4; ni++)
                        asm volatile(
                            "mma.sync.aligned.m16n8k16.row.col.f32.f16.f16.f32 "
                            "{%0,%1,%2,%3}, {%4,%5,%6,%7}, {%8,%9}, {%0,%1,%2,%3};"
                            : "+f"(acc[mi][ni][0]), "+f"(acc[mi][ni][1]),
                              "+f"(acc[mi][ni][2]), "+f"(acc[mi][ni][3])
                            : "r"(af[mi][0]), "r"(af[mi][1]), "r"(af[mi][2]), "r"(af[mi][3]),
                              "r"(wq[ni][2*kk2]), "r"(wq[ni][2*kk2+1]));
            }
        }
    }

#pragma unroll
    for (int mi = 0; mi < 4; mi++) {
        int r0 = row0 + wm*64 + mi*16 + g;
#pragma unroll
        for (int ni = 0; ni < 4; ni++) {
            int c = col0 + wn*32 + ni*8 + 2*q;
            float b0 = 0.f, b1 = 0.f;
            if (bias) { b0 = bias[c]; b1 = bias[c+1]; }
            *(float2*)(C + (size_t)r0     * N + c) = make_float2(acc[mi][ni][0]+b0, acc[mi][ni][1]+b1);
            *(float2*)(C + (size_t)(r0+8) * N + c) = make_float2(acc[mi][ni][2]+b0, acc[mi][ni][3]+b1);
        }
    }
#undef LOAD_STAGE_G
}

// ---------------- merged GRU pointwise: layer0 step k + layer1 step k-1 ----------------
__device__ __forceinline__ float sigm(float x) { return 1.f / (1.f + __expf(-x)); }
__device__ __forceinline__ float tanh_fast(float x) { return 2.f / (1.f + __expf(-2.f*x)) - 1.f; }

__global__ void k_pw(const float* __restrict__ bih0, const float* __restrict__ bhh0,
                     const float* __restrict__ bih1, const float* __restrict__ bhh1,
                     const float* __restrict__ h0in, float* __restrict__ h0out,
                     __half* __restrict__ h0hout,
                     const float* __restrict__ h1in, float* __restrict__ h1out,
                     __half* __restrict__ h1hout, __half* __restrict__ yout, int k)
{
    const int T = d_T[0];
    int i4 = blockIdx.x * blockDim.x + threadIdx.x;
    if (i4 >= BH/4) return;
    int i = i4 << 2;
    int b = i >> 9, j = i & (HSZ-1);
    int base = b*H3 + j;

    const float* Xs;  const float* Gs;
    const float* bi;  const float* bh;
    const float* hin; float* hout; __half* hhout;
    bool writeY;

    if (blockIdx.y == 0) {
        if (k >= T) return;
        Xs = d_A0; Gs = d_G0; bi = bih0; bh = bhh0;
        hin = h0in; hout = h0out; hhout = h0hout; writeY = false;
    } else {
        if (k < 1 || k-1 >= T) return;
        Xs = d_A1; Gs = d_G1; bi = bih1; bh = bhh1;
        hin = h1in; hout = h1out; hhout = h1hout; writeY = true;
    }

    float4 ar = *(const float4*)(Xs + base);
    float4 az = *(const float4*)(Xs + base + HSZ);
    float4 an = *(const float4*)(Xs + base + 2*HSZ);
    float4 gr = *(const float4*)(Gs + base);
    float4 gz = *(const float4*)(Gs + base + HSZ);
    float4 gn = *(const float4*)(Gs + base + 2*HSZ);
    float4 h  = *(const float4*)(hin + i);
    float4 bir = *(const float4*)(bi + j);
    float4 biz = *(const float4*)(bi + j + HSZ);
    float4 bin = *(const float4*)(bi + j + 2*HSZ);
    float4 bhr = *(const float4*)(bh + j);
    float4 bhz = *(const float4*)(bh + j + HSZ);
    float4 bhn = *(const float4*)(bh + j + 2*HSZ);

    float hn[4];
    const float* pxr=(const float*)&ar; const float* pxz=(const float*)&az; const float* pxn=(const float*)&an;
    const float* pgr=(const float*)&gr; const float* pgz=(const float*)&gz; const float* pgn=(const float*)&gn;
    const float* ph =(const float*)&h;
    const float* pir=(const float*)&bir; const float* piz=(const float*)&biz; const float* pin=(const float*)&bin;
    const float* phr=(const float*)&bhr; const float* phz=(const float*)&bhz; const float* phn=(const float*)&bhn;
#pragma unroll
    for (int e = 0; e < 4; e++) {
        float r = sigm(pxr[e]+pir[e] + pgr[e]+phr[e]);
        float z = sigm(pxz[e]+piz[e] + pgz[e]+phz[e]);
        float n = tanh_fast(pxn[e]+pin[e] + r * (pgn[e]+phn[e]));
        hn[e] = (1.f - z) * n + z * ph[e];
    }

    *(float4*)(hout + i) = make_float4(hn[0], hn[1], hn[2], hn[3]);
    __half2 p0 = __floats2half2_rn(hn[0], hn[1]);
    __half2 p1 = __floats2half2_rn(hn[2], hn[3]);
    ((__half2*)(hhout + i))[0] = p0;
    ((__half2*)(hhout + i))[1] = p1;
    if (writeY) {
        ((__half2*)(yout + i))[0] = p0;
        ((__half2*)(yout + i))[1] = p1;
    }
}

// ---------------- host launch ----------------
extern "C" void kernel_launch(void* const* d_in, const int* in_sizes, int n_in,
                              void* d_out, int out_size)
{
    const float* x    = (const float*)d_in[0];
    const float* Wih0 = (const float*)d_in[1];
    const float* Whh0 = (const float*)d_in[2];
    const float* bih0 = (const float*)d_in[3];
    const float* bhh0 = (const float*)d_in[4];
    const float* Wih1 = (const float*)d_in[5];
    const float* Whh1 = (const float*)d_in[6];
    const float* bih1 = (const float*)d_in[7];
    const float* bhh1 = (const float*)d_in[8];
    const float* Wout = (const float*)d_in[9];
    const float* bout = (const float*)d_in[10];
    const int*   psi  = (const int*)d_in[11];
    float* out = (float*)d_out;

    cudaFuncSetAttribute(gemm3, cudaFuncAttributeMaxDynamicSharedMemorySize, SMEM_G);

    float *p_h0fA,*p_h0fB,*p_h1fA,*p_h1fB,*p_A0,*p_G0,*p_G1,*p_A1;
    __half *p_h0hA,*p_h0hB,*p_h1hA,*p_h1hB,*p_Y1h,*p_xh,*p_Wih0h,*p_Whh0h,*p_Wih1h,*p_Whh1h,*p_Wouth;
    int *p_rowoff;
    cudaGetSymbolAddress((void**)&p_h0fA, d_h0fA);
    cudaGetSymbolAddress((void**)&p_h0fB, d_h0fB);
    cudaGetSymbolAddress((void**)&p_h1fA, d_h1fA);
    cudaGetSymbolAddress((void**)&p_h1fB, d_h1fB);
    cudaGetSymbolAddress((void**)&p_h0hA, d_h0hA);
    cudaGetSymbolAddress((void**)&p_h0hB, d_h0hB);
    cudaGetSymbolAddress((void**)&p_h1hA, d_h1hA);
    cudaGetSymbolAddress((void**)&p_h1hB, d_h1hB);
    cudaGetSymbolAddress((void**)&p_A0,   d_A0);
    cudaGetSymbolAddress((void**)&p_G0,   d_G0);
    cudaGetSymbolAddress((void**)&p_G1,   d_G1);
    cudaGetSymbolAddress((void**)&p_A1,   d_A1);
    cudaGetSymbolAddress((void**)&p_Y1h,  d_Y1h);
    cudaGetSymbolAddress((void**)&p_xh,   d_xh);
    cudaGetSymbolAddress((void**)&p_Wih0h,d_Wih0h);
    cudaGetSymbolAddress((void**)&p_Whh0h,d_Whh0h);
    cudaGetSymbolAddress((void**)&p_Wih1h,d_Wih1h);
    cudaGetSymbolAddress((void**)&p_Whh1h,d_Whh1h);
    cudaGetSymbolAddress((void**)&p_Wouth,d_Wouth);
    cudaGetSymbolAddress((void**)&p_rowoff, d_rowoff);

    const int PWI = (BH + 255) / 256;
    const int PW4 = (BH/4 + 255) / 256;

    k_init_first<<<PWI, 256>>>(psi);
    k_rank<<<(NSZ + 255) / 256, 256>>>(psi);
    k_convA<<<(BSZ*INSZ/4 + 255)/256, 256>>>(x, Wih0, Wout);
    k_convB<<<(H3*HSZ/4   + 255)/256, 256>>>(Whh0, Wih1, Whh1);

    // A0 = x . Wih0^T  (biases added in pw)
    gemm3<<<dim3(H3/BN, BSZ/BM, 1), 256, SMEM_G>>>(
        p_xh, p_Wih0h, p_A0,  p_xh, p_Wih0h, p_A0,  p_xh, p_Wih0h, p_A0,
        BSZ, H3, INSZ, nullptr, nullptr, 0, 0, 0);

    float  *h0f_in = p_h0fA, *h0f_out = p_h0fB;
    float  *h1f_in = p_h1fA, *h1f_out = p_h1fB;
    __half *h0h_in = p_h0hA, *h0h_out = p_h0hB;
    __half *h1h_in = p_h1hA, *h1h_out = p_h1hB;

    // wavefront: iteration k computes layer0 step k and layer1 step k-1
    for (int k = 0; k <= T_MAX; k++) {
        gemm3<<<dim3(H3/BN, BSZ/BM, 3), 256, SMEM_G>>>(
            h0h_in, p_Whh0h, p_G0,     // z=0: G0(k)   = h0(k-1) . Whh0^T
            h1h_in, p_Whh1h, p_G1,     // z=1: G1(k-1) = h1(k-2) . Whh1^T
            h0h_in, p_Wih1h, p_A1,     // z=2: A1(k-1) = h0(k-1) . Wih1^T
            BSZ, H3, HSZ, nullptr, nullptr, k, k-1, 1);

        __half* yptr = p_Y1h + (size_t)(k > 0 ? k-1 : 0) * BH;
        k_pw<<<dim3(PW4, 2), 256>>>(bih0, bhh0, bih1, bhh1,
                                    h0f_in, h0f_out, h0h_out,
                                    h1f_in, h1f_out, h1h_out, yptr, k);

        float* tf; __half* th;
        tf = h0f_in; h0f_in = h0f_out; h0f_out = tf;
        tf = h1f_in; h1f_in = h1f_out; h1f_out = tf;
        th = h0h_in; h0h_in = h0h_out; h0h_out = th;
        th = h1h_in; h1h_in = h1h_out; h1h_out = th;
    }

    // gathered output GEMM: out[N, OUT] = Y1h[rowoff[j]] . Wout^T + bout
    gemm3<<<dim3(OUTSZ/BN, NSZ/BM, 1), 256, SMEM_G>>>(
        p_Y1h, p_Wouth, out,  p_Y1h, p_Wouth, out,  p_Y1h, p_Wouth, out,
        NSZ, OUTSZ, HSZ, p_rowoff, bout, 0, 0, 0);

    (void)in_sizes; (void)n_in; (void)out_size;
}